// round 1
// baseline (speedup 1.0000x reference)
#include <cuda_runtime.h>
#include <math.h>

#define BATCH 2048
#define LSEQ  70
#define DIN   15
#define HID   16
#define NF    4
#define KW    40
#define CDIM  20          // DIN + 1 + NF
#define LP    31          // LSEQ - KW + 1
#define Z0    64
#define NOUT  128         // 2*Z0
#define SIGCH 8420        // C + C^2 + C^3

#define KSPLIT 12
#define KCHUNK 704        // 12*704 = 8448 >= 8420, multiple of 32

// Scratch (static device arrays: allocation-free per harness rules)
__device__ float g_sig[(size_t)BATCH * SIGCH];            // 69 MB
__device__ float g_zpart[(size_t)KSPLIT * BATCH * NOUT];  // 12 MB

// ---------------------------------------------------------------------------
// Kernel 1: per-batch path (conv chain) + depth-3 signature
// One block per batch, 224 threads (7 warps).
// ---------------------------------------------------------------------------
__global__ __launch_bounds__(224) void sig_kernel(
    const float* __restrict__ x,    // (B, L, DIN)
    const float* __restrict__ w1,   // (HID, DIN, KW)
    const float* __restrict__ b1,   // (HID)
    const float* __restrict__ w2,   // (HID, HID)
    const float* __restrict__ b2,   // (HID)
    const float* __restrict__ w3,   // (NF, HID)
    const float* __restrict__ b3)   // (NF)
{
    // xs: (L+1) rows x DIN (row 70 zero-padded for sliding window overrun)
    __shared__ float xs[(LSEQ + 1) * DIN];          // 1065
    __shared__ float h1s[HID * LP];                 // 496  (relu'd conv1)
    // ubuf: conv1 phase = w1 copy (9600 floats); later reused:
    //   paths[0..619], h2s[640..1135], dsm[1152..1171]
    __shared__ float ubuf[HID * DIN * KW];          // 9600 floats = 38.4 KB

    const int b = blockIdx.x;
    const int t = threadIdx.x;

    // ---- load x[b] and w1 into smem ----
    for (int i = t; i < LSEQ * DIN; i += 224) xs[i] = x[(size_t)b * LSEQ * DIN + i];
    if (t < DIN) xs[LSEQ * DIN + t] = 0.f;          // pad row
    for (int i = t; i < HID * DIN * KW; i += 224) ubuf[i] = w1[i];
    __syncthreads();

    // ---- conv1 (VALID, kernel 40): 128 threads, each (o, 4 l's), sliding window ----
    if (t < 128) {
        const int o  = t >> 3;
        const int lc = t & 7;
        const int l0 = lc * 4;
        float a0 = 0.f, a1 = 0.f, a2 = 0.f, a3 = 0.f;
        const float* wrow = &ubuf[o * DIN * KW];
        for (int c = 0; c < DIN; ++c) {
            float xw0 = xs[(l0 + 0) * DIN + c];
            float xw1 = xs[(l0 + 1) * DIN + c];
            float xw2 = xs[(l0 + 2) * DIN + c];
            const float* wc = wrow + c * KW;
            #pragma unroll 8
            for (int k = 0; k < KW; ++k) {
                float xw3 = xs[(l0 + k + 3) * DIN + c];
                float w = wc[k];
                a0 = fmaf(w, xw0, a0);
                a1 = fmaf(w, xw1, a1);
                a2 = fmaf(w, xw2, a2);
                a3 = fmaf(w, xw3, a3);
                xw0 = xw1; xw1 = xw2; xw2 = xw3;
            }
        }
        float bias = b1[o];
        if (l0 + 0 < LP) h1s[o * LP + l0 + 0] = fmaxf(a0 + bias, 0.f);
        if (l0 + 1 < LP) h1s[o * LP + l0 + 1] = fmaxf(a1 + bias, 0.f);
        if (l0 + 2 < LP) h1s[o * LP + l0 + 2] = fmaxf(a2 + bias, 0.f);
        if (l0 + 3 < LP) h1s[o * LP + l0 + 3] = fmaxf(a3 + bias, 0.f);
    }
    __syncthreads();   // w1 copy in ubuf now dead; reuse space below

    float* paths = ubuf;             // [LP*CDIM] = 620
    float* h2s   = ubuf + 640;       // [HID*LP]  = 496
    float* dsm   = ubuf + 1152;      // [CDIM]    = 20

    // ---- conv2 (1x1) + relu ----
    for (int idx = t; idx < HID * LP; idx += 224) {
        int o = idx / LP, l = idx % LP;
        float s = b2[o];
        #pragma unroll
        for (int c2 = 0; c2 < HID; ++c2)
            s = fmaf(w2[o * HID + c2], h1s[c2 * LP + l], s);
        h2s[idx] = fmaxf(s, 0.f);
    }
    __syncthreads();

    // ---- conv3 (1x1) + assemble path [orig(15) | time(1) | conv_out(4)] ----
    for (int idx = t; idx < LP * CDIM; idx += 224) {
        int l = idx / CDIM, c = idx % CDIM;
        float v;
        if (c < DIN) {
            v = xs[(KW - 1 + l) * DIN + c];
        } else if (c == DIN) {
            v = (float)l * (1.0f / (LP - 1));
        } else {
            int f = c - DIN - 1;
            float s = b3[f];
            #pragma unroll
            for (int c2 = 0; c2 < HID; ++c2)
                s = fmaf(w3[f * HID + c2], h2s[c2 * LP + l], s);
            v = s;
        }
        paths[idx] = v;
    }
    __syncthreads();

    // ---- depth-3 signature (Chen's relation, 1 FMA per s3 elem per step) ----
    // thread t < 200 owns (i,j) pairs p0=(i0=t/20, j=t%20) and p1=(i0+10, j)
    const int i0 = t / CDIM;
    const int j0 = t % CDIM;
    float s1a = 0.f, s1b = 0.f, s2a = 0.f, s2b = 0.f;
    float s3a[CDIM], s3b[CDIM];
    #pragma unroll
    for (int k = 0; k < CDIM; ++k) { s3a[k] = 0.f; s3b[k] = 0.f; }

    for (int s = 0; s < LP; ++s) {
        if (t < CDIM)
            dsm[t] = paths[s * CDIM + t] - (s ? paths[(s - 1) * CDIM + t] : 0.f);
        __syncthreads();
        if (t < 200) {
            float dj  = dsm[j0];
            float dia = dsm[i0];
            float dib = dsm[i0 + 10];
            // A = s2 + dj*(d_i/6 + s1_i/2)  ; n3 = s3 + A*d_k
            float A0 = fmaf(dj, fmaf(dia, 1.f / 6.f, 0.5f * s1a), s2a);
            float A1 = fmaf(dj, fmaf(dib, 1.f / 6.f, 0.5f * s1b), s2b);
            // n2 = s2 + dj*(s1_i + d_i/2)
            s2a = fmaf(dj, fmaf(dia, 0.5f, s1a), s2a);
            s2b = fmaf(dj, fmaf(dib, 0.5f, s1b), s2b);
            s1a += dia;
            s1b += dib;
            #pragma unroll
            for (int k = 0; k < CDIM; ++k) {
                float dk = dsm[k];
                s3a[k] = fmaf(A0, dk, s3a[k]);
                s3b[k] = fmaf(A1, dk, s3b[k]);
            }
        }
        __syncthreads();
    }

    // ---- write signature: [s1(20) | s2(400) | s3(8000)] ----
    size_t base = (size_t)b * SIGCH;
    if (t < CDIM) g_sig[base + t] = paths[(LP - 1) * CDIM + t];   // s1 = path[-1]
    if (t < 200) {
        g_sig[base + CDIM + t]       = s2a;
        g_sig[base + CDIM + 200 + t] = s2b;
        size_t s3base = base + CDIM + CDIM * CDIM;
        #pragma unroll
        for (int k = 0; k < CDIM; ++k) {
            g_sig[s3base + (size_t)t * CDIM + k]         = s3a[k];
            g_sig[s3base + (size_t)(t + 200) * CDIM + k] = s3b[k];
        }
    }
}

// ---------------------------------------------------------------------------
// Kernel 2: split-K fp32 GEMM  z_part[kz] = sig_tile @ w_out^T (chunk of K)
// TM=128 (batches) x TN=128 (all outputs), KB=32, 256 threads, 8x8 microtile
// ---------------------------------------------------------------------------
#define TM 128
#define TN 128
#define KB 32

__global__ __launch_bounds__(256) void gemm_kernel(const float* __restrict__ wout)
{
    __shared__ float As[TM][KB + 1];   // [m][k], pad to kill m-stride conflicts
    __shared__ float Bs[KB][TN + 1];   // [k][n], pad to kill write conflicts

    const int m0    = blockIdx.x * TM;
    const int kz    = blockIdx.y;
    const int kbase = kz * KCHUNK;
    const int t  = threadIdx.x;
    const int tx = t & 15;     // n-group
    const int ty = t >> 4;     // m-group

    float acc[8][8];
    #pragma unroll
    for (int i = 0; i < 8; ++i)
        #pragma unroll
        for (int j = 0; j < 8; ++j) acc[i][j] = 0.f;

    for (int kt = 0; kt < KCHUNK; kt += KB) {
        const int k0 = kbase + kt;
        // load A tile: sig[m0+m][k0+c], coalesced over c
        #pragma unroll
        for (int i = 0; i < 16; ++i) {
            int idx = t + i * 256;
            int m = idx >> 5, c = idx & 31;
            int k = k0 + c;
            As[m][c] = (k < SIGCH) ? g_sig[(size_t)(m0 + m) * SIGCH + k] : 0.f;
        }
        // load B tile: wout[n][k0+c], coalesced over c
        #pragma unroll
        for (int i = 0; i < 16; ++i) {
            int idx = t + i * 256;
            int n = idx >> 5, c = idx & 31;
            int k = k0 + c;
            Bs[c][n] = (k < SIGCH) ? wout[(size_t)n * SIGCH + k] : 0.f;
        }
        __syncthreads();
        #pragma unroll
        for (int kk = 0; kk < KB; ++kk) {
            float a[8], bb[8];
            #pragma unroll
            for (int i = 0; i < 8; ++i) a[i] = As[ty * 8 + i][kk];
            #pragma unroll
            for (int j = 0; j < 8; ++j) bb[j] = Bs[kk][tx * 8 + j];
            #pragma unroll
            for (int i = 0; i < 8; ++i)
                #pragma unroll
                for (int j = 0; j < 8; ++j)
                    acc[i][j] = fmaf(a[i], bb[j], acc[i][j]);
        }
        __syncthreads();
    }

    float* zp = &g_zpart[((size_t)kz * BATCH + m0) * NOUT];
    #pragma unroll
    for (int i = 0; i < 8; ++i)
        #pragma unroll
        for (int j = 0; j < 8; ++j)
            zp[(size_t)(ty * 8 + i) * NOUT + tx * 8 + j] = acc[i][j];
}

// ---------------------------------------------------------------------------
// Kernel 3: reduce split-K partials + bias; mean | softplus(std) layout
// out[0 : B*64]        = z[:, :64]
// out[B*64 : 2*B*64]   = softplus(z[:, 64:128])
// ---------------------------------------------------------------------------
__global__ __launch_bounds__(256) void epi_kernel(const float* __restrict__ bout,
                                                  float* __restrict__ out)
{
    int idx = blockIdx.x * 256 + threadIdx.x;
    if (idx >= BATCH * NOUT) return;
    int b = idx / NOUT, n = idx % NOUT;
    float s = bout[n];
    #pragma unroll
    for (int z = 0; z < KSPLIT; ++z)
        s += g_zpart[((size_t)z * BATCH + b) * NOUT + n];
    if (n < Z0) {
        out[(size_t)b * Z0 + n] = s;
    } else {
        float v = fmaxf(s, 0.f) + log1pf(expf(-fabsf(s)));   // stable softplus
        out[(size_t)BATCH * Z0 + (size_t)b * Z0 + (n - Z0)] = v;
    }
}

// ---------------------------------------------------------------------------
extern "C" void kernel_launch(void* const* d_in, const int* in_sizes, int n_in,
                              void* d_out, int out_size)
{
    const float* x    = (const float*)d_in[0];
    // d_in[1] = observed_tp (unused by the reference computation)
    const float* w1   = (const float*)d_in[2];
    const float* b1   = (const float*)d_in[3];
    const float* w2   = (const float*)d_in[4];
    const float* b2   = (const float*)d_in[5];
    const float* w3   = (const float*)d_in[6];
    const float* b3   = (const float*)d_in[7];
    const float* wout = (const float*)d_in[8];
    const float* bout = (const float*)d_in[9];
    float* out = (float*)d_out;

    sig_kernel<<<BATCH, 224>>>(x, w1, b1, w2, b2, w3, b3);
    gemm_kernel<<<dim3(BATCH / TM, KSPLIT), 256>>>(wout);
    epi_kernel<<<(BATCH * NOUT + 255) / 256, 256>>>(bout, out);
}